// round 1
// baseline (speedup 1.0000x reference)
#include <cuda_runtime.h>
#include <math.h>

#define BATCH 512
#define SEQ   256
#define EMBED 384
#define HDIM  64
#define NROWS (BATCH * SEQ)   // 131072

// Scratch for projected Q/K/V (33.5 MB each). __device__ globals are the
// sanctioned scratch mechanism (no allocations allowed in kernel_launch).
__device__ float g_Q[(size_t)NROWS * HDIM];
__device__ float g_K[(size_t)NROWS * HDIM];
__device__ float g_V[(size_t)NROWS * HDIM];

// ---------------------------------------------------------------------------
// Projection GEMM: [131072, 384] x [384, 64] (x3 fused in N) -> g_Q/g_K/g_V
// Block tile 128(M) x 192(N), K-chunk 32. 384 threads (16 x 24), 8x8 micro.
// ---------------------------------------------------------------------------
#define PBM 128
#define PBK 32
#define PTHREADS 384

__global__ __launch_bounds__(PTHREADS) void proj_kernel(
    const float* __restrict__ X,
    const float* __restrict__ Wq,
    const float* __restrict__ Wk,
    const float* __restrict__ Wv)
{
    __shared__ float Xs[PBK][PBM + 1];   // transposed: Xs[k][row], pad -> conflict-free
    __shared__ float Ws[PBK][192];       // Q | K | V columns

    const int tid = threadIdx.x;
    const int ty = tid / 24;             // 0..15 -> row group (8 rows)
    const int tx = tid % 24;             // 0..23 -> col group (8 cols)
    const int row0 = blockIdx.x * PBM;

    float acc[8][8];
#pragma unroll
    for (int r = 0; r < 8; ++r)
#pragma unroll
        for (int c = 0; c < 8; ++c) acc[r][c] = 0.0f;

    for (int k0 = 0; k0 < EMBED; k0 += PBK) {
        // --- load X tile (128 x 32), transpose into smem ---
        for (int idx = tid; idx < PBM * (PBK / 4); idx += PTHREADS) {
            const int r  = idx >> 3;     // 0..127
            const int kq = idx & 7;      // 0..7 (float4 along k)
            const float4 v = *(const float4*)(X + (size_t)(row0 + r) * EMBED + k0 + kq * 4);
            Xs[kq * 4 + 0][r] = v.x;
            Xs[kq * 4 + 1][r] = v.y;
            Xs[kq * 4 + 2][r] = v.z;
            Xs[kq * 4 + 3][r] = v.w;
        }
        // --- load W tile (32 x 192) ---
        for (int idx = tid; idx < PBK * 48; idx += PTHREADS) {
            const int kk = idx / 48;
            const int c4 = idx % 48;     // float4 column index (0..47)
            const float* Wm = (c4 < 16) ? Wq : ((c4 < 32) ? Wk : Wv);
            const int d4 = c4 & 15;
            const float4 v = *(const float4*)(Wm + (size_t)(k0 + kk) * HDIM + d4 * 4);
            *(float4*)(&Ws[kk][c4 * 4]) = v;
        }
        __syncthreads();

#pragma unroll 4
        for (int k = 0; k < PBK; ++k) {
            float a[8];
#pragma unroll
            for (int r = 0; r < 8; ++r) a[r] = Xs[k][ty * 8 + r];
            const float4 b0 = *(const float4*)(&Ws[k][tx * 8]);
            const float4 b1 = *(const float4*)(&Ws[k][tx * 8 + 4]);
            const float b[8] = {b0.x, b0.y, b0.z, b0.w, b1.x, b1.y, b1.z, b1.w};
#pragma unroll
            for (int r = 0; r < 8; ++r)
#pragma unroll
                for (int c = 0; c < 8; ++c)
                    acc[r][c] = fmaf(a[r], b[c], acc[r][c]);
        }
        __syncthreads();
    }

    // --- epilogue: tx 0..7 -> Q, 8..15 -> K, 16..23 -> V ---
    float* Og = (tx < 8) ? g_Q : ((tx < 16) ? g_K : g_V);
    const int d0 = (tx & 7) * 8;
#pragma unroll
    for (int r = 0; r < 8; ++r) {
        const size_t o = (size_t)(row0 + ty * 8 + r) * HDIM + d0;
        float4 v0, v1;
        v0.x = acc[r][0]; v0.y = acc[r][1]; v0.z = acc[r][2]; v0.w = acc[r][3];
        v1.x = acc[r][4]; v1.y = acc[r][5]; v1.z = acc[r][6]; v1.w = acc[r][7];
        *(float4*)(Og + o)     = v0;
        *(float4*)(Og + o + 4) = v1;
    }
}

// ---------------------------------------------------------------------------
// Attention: one block per (batch, 64-query tile). Whole K/V/scores in smem.
// 256 threads as 16(ty: query rows) x 16(tx: key cols / out dims), 4x4 micro.
// ---------------------------------------------------------------------------
#define KT_LD  260   // Kt row stride (floats), mult of 4 -> float4 aligned
#define QT_LD  68
#define SS_LD  257

// floats: Kt 64*260 + Vs 256*64 + Qt 64*68 + Ss 64*257 + rinv 64
#define SM_KT   0
#define SM_VS   (SM_KT + 64 * KT_LD)            // 16640
#define SM_QT   (SM_VS + 256 * 64)              // 33024
#define SM_SS   (SM_QT + 64 * QT_LD)            // 37376
#define SM_RI   (SM_SS + 64 * SS_LD)            // 53824
#define SM_FLOATS (SM_RI + 64)                  // 53888
#define SM_BYTES  (SM_FLOATS * 4)               // 215552

__global__ __launch_bounds__(256) void attn_kernel(float* __restrict__ Out)
{
    extern __shared__ float sm[];
    float* Kt   = sm + SM_KT;   // [64 kd][KT_LD] (transposed keys)
    float* Vs   = sm + SM_VS;   // [256 j][64 d]
    float* Qt   = sm + SM_QT;   // [64 kd][QT_LD] (transposed queries)
    float* Ss   = sm + SM_SS;   // [64 i][SS_LD] scores
    float* rinv = sm + SM_RI;   // [64] 1/rowsum

    const int tid = threadIdx.x;
    const int qt  = blockIdx.x;          // 0..3
    const int b   = blockIdx.y;          // 0..511
    const int kvlen = (qt + 1) * 64;

    const float* Kg = g_K + (size_t)b * SEQ * HDIM;
    const float* Vg = g_V + (size_t)b * SEQ * HDIM;
    const float* Qg = g_Q + ((size_t)b * SEQ + qt * 64) * HDIM;

    // --- load K transposed (j across lanes -> conflict-free smem stores) ---
    for (int idx = tid; idx < kvlen * 16; idx += 256) {
        const int j  = (idx & 31) + ((idx >> 9) << 5);
        const int q4 = (idx >> 5) & 15;
        const float4 v = *(const float4*)(Kg + (size_t)j * HDIM + q4 * 4);
        Kt[(q4 * 4 + 0) * KT_LD + j] = v.x;
        Kt[(q4 * 4 + 1) * KT_LD + j] = v.y;
        Kt[(q4 * 4 + 2) * KT_LD + j] = v.z;
        Kt[(q4 * 4 + 3) * KT_LD + j] = v.w;
    }
    // --- load V (dense copy) ---
    for (int idx = tid; idx < kvlen * 16; idx += 256)
        *(float4*)(Vs + idx * 4) = *(const float4*)(Vg + (size_t)idx * 4);
    // --- load Q transposed ---
    for (int idx = tid; idx < 64 * 16; idx += 256) {
        const int i  = (idx & 31) + ((idx >> 9) << 5);
        const int q4 = (idx >> 5) & 15;
        const float4 v = *(const float4*)(Qg + (size_t)i * HDIM + q4 * 4);
        Qt[(q4 * 4 + 0) * QT_LD + i] = v.x;
        Qt[(q4 * 4 + 1) * QT_LD + i] = v.y;
        Qt[(q4 * 4 + 2) * QT_LD + i] = v.z;
        Qt[(q4 * 4 + 3) * QT_LD + i] = v.w;
    }
    __syncthreads();

    const int i0 = (tid / 16) * 4;       // query rows of this thread
    const int tx = tid % 16;
    const float scale = 0.125f;          // 1/sqrt(64)

    // --- phase 1: S = scale * Q K^T, causal-masked ---
    for (int jt = 0; jt <= qt; ++jt) {
        const int j0 = jt * 64 + tx * 4;
        float acc[4][4];
#pragma unroll
        for (int r = 0; r < 4; ++r)
#pragma unroll
            for (int c = 0; c < 4; ++c) acc[r][c] = 0.0f;

#pragma unroll 16
        for (int kd = 0; kd < 64; ++kd) {
            const float4 av = *(const float4*)(Qt + kd * QT_LD + i0);
            const float4 bv = *(const float4*)(Kt + kd * KT_LD + j0);
            const float a[4] = {av.x, av.y, av.z, av.w};
            const float bb[4] = {bv.x, bv.y, bv.z, bv.w};
#pragma unroll
            for (int r = 0; r < 4; ++r)
#pragma unroll
                for (int c = 0; c < 4; ++c)
                    acc[r][c] = fmaf(a[r], bb[c], acc[r][c]);
        }
#pragma unroll
        for (int r = 0; r < 4; ++r) {
            const int qglob = qt * 64 + i0 + r;
#pragma unroll
            for (int c = 0; c < 4; ++c) {
                const int kglob = j0 + c;
                Ss[(i0 + r) * SS_LD + kglob] =
                    (kglob <= qglob) ? acc[r][c] * scale : -3.0e38f;
            }
        }
    }
    __syncthreads();

    // --- phase 2: row softmax (4 threads per row), keep 1/sum ---
    {
        const int row = tid >> 2;
        const int c   = tid & 3;
        float m = -3.4e38f;
        for (int j = c; j < kvlen; j += 4)
            m = fmaxf(m, Ss[row * SS_LD + j]);
        m = fmaxf(m, __shfl_xor_sync(0xffffffffu, m, 1));
        m = fmaxf(m, __shfl_xor_sync(0xffffffffu, m, 2));
        float s = 0.0f;
        for (int j = c; j < kvlen; j += 4) {
            const float e = __expf(Ss[row * SS_LD + j] - m);
            Ss[row * SS_LD + j] = e;
            s += e;
        }
        s += __shfl_xor_sync(0xffffffffu, s, 1);
        s += __shfl_xor_sync(0xffffffffu, s, 2);
        if (c == 0) rinv[row] = 1.0f / s;
    }
    __syncthreads();

    // --- phase 3: O = P V (1/sum folded into epilogue) ---
    {
        const int d0 = tx * 4;
        float acc[4][4];
#pragma unroll
        for (int r = 0; r < 4; ++r)
#pragma unroll
            for (int c = 0; c < 4; ++c) acc[r][c] = 0.0f;

#pragma unroll 8
        for (int j = 0; j < kvlen; ++j) {
            const float4 bv = *(const float4*)(Vs + j * 64 + d0);
            const float bb[4] = {bv.x, bv.y, bv.z, bv.w};
            float a[4];
#pragma unroll
            for (int r = 0; r < 4; ++r) a[r] = Ss[(i0 + r) * SS_LD + j];
#pragma unroll
            for (int r = 0; r < 4; ++r)
#pragma unroll
                for (int c = 0; c < 4; ++c)
                    acc[r][c] = fmaf(a[r], bb[c], acc[r][c]);
        }

        float* Og = Out + ((size_t)b * SEQ + qt * 64) * HDIM;
#pragma unroll
        for (int r = 0; r < 4; ++r) {
            const float inv = rinv[i0 + r];
            float4 v;
            v.x = acc[r][0] * inv; v.y = acc[r][1] * inv;
            v.z = acc[r][2] * inv; v.w = acc[r][3] * inv;
            *(float4*)(Og + (size_t)(i0 + r) * HDIM + d0) = v;
        }
    }
}

// ---------------------------------------------------------------------------
extern "C" void kernel_launch(void* const* d_in, const int* in_sizes, int n_in,
                              void* d_out, int out_size)
{
    const float* X  = (const float*)d_in[0];   // input_tensor [512,256,384]
    const float* Wk = (const float*)d_in[1];   // [384,64]
    const float* Wq = (const float*)d_in[2];   // [384,64]
    const float* Wv = (const float*)d_in[3];   // [384,64]
    float* Out = (float*)d_out;                // [512,256,64]

    (void)in_sizes; (void)n_in; (void)out_size;

    cudaFuncSetAttribute(attn_kernel,
                         cudaFuncAttributeMaxDynamicSharedMemorySize, SM_BYTES);

    proj_kernel<<<NROWS / PBM, PTHREADS>>>(X, Wq, Wk, Wv);

    dim3 grid(SEQ / 64, BATCH);
    attn_kernel<<<grid, 256, SM_BYTES>>>(Out);
}